// round 14
// baseline (speedup 1.0000x reference)
#include <cuda_runtime.h>
#include <cuda_bf16.h>
#include <cstdint>

#define N_NODES 50000
#define N_EDGES 800000
#define D 128
#define NL 3
#define BN_EPSF 1e-5f

// ---------------- scratch (device globals; no allocs allowed) ----------------
__device__ __align__(16) float g_agg[N_NODES * D];
__device__ __align__(16) float g_x[N_NODES * D];
__device__ __align__(16) float g_h[N_NODES * D];
__device__ __align__(16) int   g_off[N_NODES + 4];
__device__ __align__(16) int   g_cur[N_NODES];
__device__ __align__(16) int   g_srcs[N_EDGES];
__device__ __align__(16) float g_ws[N_EDGES];
__device__ __align__(16) float g_stats[NL * 2 * D];      // per-layer [sum|sumsq]
__device__ __align__(16) int   g_bsum[64];
__device__ __align__(16) float g_wt[NL * 2 * D * D];     // W^T, tf32-rounded fp32
__device__ int g_is32;

__device__ __forceinline__ uint32_t f2tf32(float v) {
    uint32_t r;
    asm("cvt.rna.tf32.f32 %0, %1;" : "=r"(r) : "f"(v));
    return r;
}

// ---------------- init: weight pre-round (tf32, transposed) + detect + zeros ----
__global__ void k_init(const float* __restrict__ W1, const float* __restrict__ W2,
                       const long long* __restrict__ ei) {
    int b = blockIdx.x, tid = threadIdx.x;
    if (b < 6) {                       // W^T tf32: wt[b][n][k] = rna(W[k][n])
        int l = b >> 1, m = b & 1;
        const float* W = (m ? W2 : W1) + l * D * D;
        float* wt = g_wt + b * D * D;
        for (int idx = tid; idx < D * D; idx += 256) {
            int k = idx >> 7, n = idx & 127;
            wt[n * D + k] = __uint_as_float(f2tf32(W[idx]));
        }
    } else if (b == 6) {               // dtype sniff + BN stats zero
        if (tid == 0) {
            int is32 = 0;
            for (int i = 0; i < 64; i++) {
                long long v = ei[i];
                if (v < 0 || v >= N_NODES) { is32 = 1; break; }
            }
            g_is32 = is32;
        }
        for (int s = tid; s < NL * 2 * D; s += 256) g_stats[s] = 0.f;
    } else {                           // zero degree counters
        int i = (b - 7) * 256 + tid;
        if (i < N_NODES) g_cur[i] = 0;
    }
}

// ---------------- CSR build ----------------
// 4 edges per thread, vectorized loads
__global__ void k_hist(const void* __restrict__ eiraw) {
    int e0 = (blockIdx.x * blockDim.x + threadIdx.x) * 4;
    if (e0 >= N_EDGES) return;
    int d4[4];
    if (g_is32) {
        int4 v = *(const int4*)((const int*)eiraw + N_EDGES + e0);
        d4[0] = v.x; d4[1] = v.y; d4[2] = v.z; d4[3] = v.w;
    } else {
        const long long* p = (const long long*)eiraw + N_EDGES + e0;
        longlong2 v0 = *(const longlong2*)p;
        longlong2 v1 = *(const longlong2*)(p + 2);
        d4[0] = (int)v0.x; d4[1] = (int)v0.y; d4[2] = (int)v1.x; d4[3] = (int)v1.y;
    }
#pragma unroll
    for (int u = 0; u < 4; u++)
        if ((unsigned)d4[u] < N_NODES) atomicAdd(&g_cur[d4[u]], 1);
}

__global__ void k_scan1() {
    __shared__ int s[1024];
    int b = blockIdx.x, tid = threadIdx.x;
    int i = b * 1024 + tid;
    int v = (i < N_NODES) ? g_cur[i] : 0;
    s[tid] = v;
    __syncthreads();
    for (int d = 1; d < 1024; d <<= 1) {
        int t = (tid >= d) ? s[tid - d] : 0;
        __syncthreads();
        s[tid] += t;
        __syncthreads();
    }
    if (i < N_NODES) g_off[i] = s[tid] - v;   // block-local exclusive
    if (tid == 1023) g_bsum[b] = s[1023];
}

// fused cross-block prefix + fixup
__global__ void k_scan3() {
    __shared__ int pre;
    if (threadIdx.x == 0) {
        int acc = 0;
        for (int b = 0; b < blockIdx.x; b++) acc += g_bsum[b];
        pre = acc;
        if (blockIdx.x == 48) g_off[N_NODES] = acc + g_bsum[48];
    }
    __syncthreads();
    int i = blockIdx.x * 1024 + threadIdx.x;
    if (i < N_NODES) {
        int o = g_off[i] + pre;
        g_off[i] = o;
        g_cur[i] = o;
    }
}

__global__ void k_scatter(const void* __restrict__ eiraw, const float* __restrict__ ew) {
    int e = blockIdx.x * blockDim.x + threadIdx.x;
    if (e >= N_EDGES) return;
    int src, dst;
    if (g_is32) {
        const int* p = (const int*)eiraw;
        src = p[e]; dst = p[N_EDGES + e];
    } else {
        const long long* p = (const long long*)eiraw;
        src = (int)p[e]; dst = (int)p[N_EDGES + e];
    }
    if ((unsigned)src >= N_NODES || (unsigned)dst >= N_NODES) return;
    int q = atomicAdd(&g_cur[dst], 1);
    g_srcs[q] = src;
    g_ws[q] = ew[e];
}

// ---------------- aggregation: one warp per node, 8 gathers in flight ----------
__global__ __launch_bounds__(256) void k_agg(const float* __restrict__ xin) {
    int warp = (blockIdx.x * blockDim.x + threadIdx.x) >> 5;
    int lane = threadIdx.x & 31;
    if (warp >= N_NODES) return;
    int beg = g_off[warp];
    int end = g_off[warp + 1];
    float4 acc = make_float4(0.f, 0.f, 0.f, 0.f);
    const float4* xr = (const float4*)xin;
    int j = beg;
    for (; j + 8 <= end; j += 8) {
        int   s[8];
        float w[8];
#pragma unroll
        for (int u = 0; u < 8; u++) { s[u] = g_srcs[j + u]; w[u] = g_ws[j + u]; }
        float4 v[8];
#pragma unroll
        for (int u = 0; u < 8; u++) v[u] = xr[s[u] * (D / 4) + lane];
#pragma unroll
        for (int u = 0; u < 8; u++) {
            acc.x += w[u] * v[u].x;
            acc.y += w[u] * v[u].y;
            acc.z += w[u] * v[u].z;
            acc.w += w[u] * v[u].w;
        }
    }
    for (; j + 2 <= end; j += 2) {
        int s0 = g_srcs[j];     float w0 = g_ws[j];
        int s1 = g_srcs[j + 1]; float w1 = g_ws[j + 1];
        float4 v0 = xr[s0 * (D / 4) + lane];
        float4 v1 = xr[s1 * (D / 4) + lane];
        acc.x += w0 * v0.x + w1 * v1.x;
        acc.y += w0 * v0.y + w1 * v1.y;
        acc.z += w0 * v0.z + w1 * v1.z;
        acc.w += w0 * v0.w + w1 * v1.w;
    }
    if (j < end) {
        int s0 = g_srcs[j]; float w0 = g_ws[j];
        float4 v0 = xr[s0 * (D / 4) + lane];
        acc.x += w0 * v0.x; acc.y += w0 * v0.y;
        acc.z += w0 * v0.z; acc.w += w0 * v0.w;
    }
    ((float4*)g_agg)[warp * (D / 4) + lane] = acc;
}

// ---------------- single-pass tf32 mma.sync fused MLP ----------------
// 64-row tiles, 256 threads, 2x4 warp grid (warp tile 32x32), 2 CTAs/SM.
// smem: sA [64][132] fp32 @ 0 (33792B), sB [128][132] fp32 @ 33792 (67584B).
// sT (64x129 f32) aliases sB; BN-reduce arrays alias sA.  total 101376B.
#define TM 64
#define SROW 132
#define OFF_A 0
#define OFF_B 33792
#define SMEM_TOT 101376

__device__ __forceinline__ void mma_tf32(float* d, const uint32_t* a,
                                         uint32_t b0, uint32_t b1) {
    asm volatile(
        "mma.sync.aligned.m16n8k8.row.col.f32.tf32.tf32.f32 "
        "{%0,%1,%2,%3}, {%4,%5,%6,%7}, {%8,%9}, {%0,%1,%2,%3};"
        : "+f"(d[0]), "+f"(d[1]), "+f"(d[2]), "+f"(d[3])
        : "r"(a[0]), "r"(a[1]), "r"(a[2]), "r"(a[3]), "r"(b0), "r"(b1));
}

// 64x128x128 GEMM, single tf32 pass, into d[2][4][4]; warp tile 32x32
__device__ __forceinline__ void gemm_tf32(const char* sm, float d[2][4][4],
                                          int rbase, int cbase, int lane) {
    int gr = lane >> 2;
    int tg = lane & 3;
    const uint32_t* A = (const uint32_t*)(sm + OFF_A);
    const uint32_t* B = (const uint32_t*)(sm + OFF_B);
#pragma unroll
    for (int k0 = 0; k0 < 16; k0++) {
        int kc = k0 * 8;
        uint32_t a[2][4];
#pragma unroll
        for (int mf = 0; mf < 2; mf++) {
            int r0 = rbase + mf * 16 + gr;
            a[mf][0] = A[r0 * SROW + kc + tg];
            a[mf][1] = A[(r0 + 8) * SROW + kc + tg];
            a[mf][2] = A[r0 * SROW + kc + tg + 4];
            a[mf][3] = A[(r0 + 8) * SROW + kc + tg + 4];
        }
#pragma unroll
        for (int nf = 0; nf < 4; nf++) {
            int n0 = cbase + nf * 8 + gr;
            uint32_t b0 = B[n0 * SROW + kc + tg];
            uint32_t b1 = B[n0 * SROW + kc + tg + 4];
            mma_tf32(d[0][nf], a[0], b0, b1);
            mma_tf32(d[1][nf], a[1], b0, b1);
        }
    }
}

__global__ __launch_bounds__(256, 2) void k_mlp(
    const float* __restrict__ xin,
    const float* __restrict__ b1, const float* __restrict__ b2,
    const float* __restrict__ epsv, int layer) {
    extern __shared__ char sm[];
    int tid = threadIdx.x, lane = tid & 31, wid = tid >> 5;
    int m0 = blockIdx.x * TM;
    int wm = wid >> 2, wn = wid & 3;          // 2 x 4 warp grid
    int rbase = wm * 32, cbase = wn * 32;
    int gr = lane >> 2, tg2 = (lane & 3) * 2;

    float* sA = (float*)(sm + OFF_A);
    float* sB = (float*)(sm + OFF_B);

    // ---- stage A = tf32((1+eps)*x + agg), zero OOB rows ----
    float e1 = 1.0f + epsv[layer];
    for (int idx = tid * 4; idx < TM * D; idx += 1024) {
        int r = idx >> 7, c = idx & 127;
        int gro = m0 + r;
        float4 v = make_float4(0.f, 0.f, 0.f, 0.f);
        if (gro < N_NODES) {
            float4 xv = *(const float4*)(xin + gro * D + c);
            float4 av = *(const float4*)(g_agg + gro * D + c);
            v.x = e1 * xv.x + av.x; v.y = e1 * xv.y + av.y;
            v.z = e1 * xv.z + av.z; v.w = e1 * xv.w + av.w;
        }
        float4 t;
        t.x = __uint_as_float(f2tf32(v.x));
        t.y = __uint_as_float(f2tf32(v.y));
        t.z = __uint_as_float(f2tf32(v.z));
        t.w = __uint_as_float(f2tf32(v.w));
        *(float4*)&sA[r * SROW + c] = t;
    }
    // ---- stage W1^T (already tf32-rounded; pure copy) ----
    {
        const float* wt = g_wt + (layer * 2 + 0) * D * D;
        for (int idx = tid * 4; idx < D * D; idx += 1024) {
            int n = idx >> 7, k = idx & 127;
            *(float4*)&sB[n * SROW + k] = *(const float4*)&wt[idx];
        }
    }
    __syncthreads();

    // ---- GEMM1: H1 = A @ W1 ----
    float d[2][4][4];
#pragma unroll
    for (int mf = 0; mf < 2; mf++)
#pragma unroll
        for (int nf = 0; nf < 4; nf++)
#pragma unroll
            for (int q = 0; q < 4; q++) d[mf][nf][q] = 0.f;
    gemm_tf32(sm, d, rbase, cbase, lane);
    __syncthreads();

    // ---- epilogue1: tf32(relu(H1 + b1)) -> back into sA ----
    {
        const float* bb = b1 + layer * D;
#pragma unroll
        for (int mf = 0; mf < 2; mf++) {
            int r0 = rbase + mf * 16 + gr;
#pragma unroll
            for (int nf = 0; nf < 4; nf++) {
                int col = cbase + nf * 8 + tg2;
                float bv0 = bb[col], bv1 = bb[col + 1];
                sA[r0 * SROW + col]           = __uint_as_float(f2tf32(fmaxf(d[mf][nf][0] + bv0, 0.f)));
                sA[r0 * SROW + col + 1]       = __uint_as_float(f2tf32(fmaxf(d[mf][nf][1] + bv1, 0.f)));
                sA[(r0 + 8) * SROW + col]     = __uint_as_float(f2tf32(fmaxf(d[mf][nf][2] + bv0, 0.f)));
                sA[(r0 + 8) * SROW + col + 1] = __uint_as_float(f2tf32(fmaxf(d[mf][nf][3] + bv1, 0.f)));
            }
        }
    }
    // ---- stage W2^T ----
    {
        const float* wt = g_wt + (layer * 2 + 1) * D * D;
        for (int idx = tid * 4; idx < D * D; idx += 1024) {
            int n = idx >> 7, k = idx & 127;
            *(float4*)&sB[n * SROW + k] = *(const float4*)&wt[idx];
        }
    }
    __syncthreads();

    // ---- GEMM2: H2 = relu(H1) @ W2 ----
#pragma unroll
    for (int mf = 0; mf < 2; mf++)
#pragma unroll
        for (int nf = 0; nf < 4; nf++)
#pragma unroll
            for (int q = 0; q < 4; q++) d[mf][nf][q] = 0.f;
    gemm_tf32(sm, d, rbase, cbase, lane);
    __syncthreads();

    // ---- epilogue2: h = H2 + b2 -> sT (zero OOB rows) ----
    float* sT = (float*)(sm + OFF_B);   // 64 x 129 floats = 33024B <= 67584B
    {
        const float* bb = b2 + layer * D;
#pragma unroll
        for (int mf = 0; mf < 2; mf++) {
            int r0 = rbase + mf * 16 + gr;
            bool v0ok = (m0 + r0) < N_NODES;
            bool v1ok = (m0 + r0 + 8) < N_NODES;
#pragma unroll
            for (int nf = 0; nf < 4; nf++) {
                int col = cbase + nf * 8 + tg2;
                float bv0 = bb[col], bv1 = bb[col + 1];
                sT[r0 * 129 + col]           = v0ok ? d[mf][nf][0] + bv0 : 0.f;
                sT[r0 * 129 + col + 1]       = v0ok ? d[mf][nf][1] + bv1 : 0.f;
                sT[(r0 + 8) * 129 + col]     = v1ok ? d[mf][nf][2] + bv0 : 0.f;
                sT[(r0 + 8) * 129 + col + 1] = v1ok ? d[mf][nf][3] + bv1 : 0.f;
            }
        }
    }
    __syncthreads();

    // ---- BN column partial sums: 2 row-halves per column (alias sA) ----
    float* sRedS = (float*)(sm + OFF_A);         // 256 floats
    float* sRedQ = (float*)(sm + OFF_A) + 256;   // 256 floats
    {
        int col = tid & 127, rq = tid >> 7;      // rq in {0,1}
        float s = 0.f, q = 0.f;
        int rlo = rq * 32;
#pragma unroll 4
        for (int r = rlo; r < rlo + 32; r++) {
            float h = sT[r * 129 + col];
            s += h; q += h * h;
        }
        sRedS[rq * 128 + col] = s;
        sRedQ[rq * 128 + col] = q;
    }
    __syncthreads();
    float* stats = g_stats + layer * 2 * D;
    if (tid < 128) {
        atomicAdd(&stats[tid], sRedS[tid] + sRedS[128 + tid]);
    } else {
        int c = tid - 128;
        atomicAdd(&stats[128 + c], sRedQ[c] + sRedQ[128 + c]);
    }
    // ---- coalesced g_h store ----
    for (int idx = tid; idx < TM * 32; idx += 256) {
        int r = idx >> 5, c4 = (idx & 31) << 2;
        int gro = m0 + r;
        if (gro < N_NODES) {
            float4 o = make_float4(sT[r * 129 + c4], sT[r * 129 + c4 + 1],
                                   sT[r * 129 + c4 + 2], sT[r * 129 + c4 + 3]);
            *(float4*)(g_h + gro * D + c4) = o;
        }
    }
}

// ---------------- BN apply + relu + residual ----------------
__global__ void k_bn(const float* __restrict__ xin, float* __restrict__ xout,
                     const float* __restrict__ gamma, const float* __restrict__ beta,
                     int layer) {
    int idx = blockIdx.x * blockDim.x + threadIdx.x;
    if (idx >= N_NODES * D / 4) return;
    int c = (idx & 31) * 4;
    const float* stats = g_stats + layer * 2 * D;
    float4 s  = *(const float4*)(stats + c);
    float4 sq = *(const float4*)(stats + D + c);
    float4 g  = *(const float4*)(gamma + layer * D + c);
    float4 be = *(const float4*)(beta + layer * D + c);
    float4 h  = ((const float4*)g_h)[idx];
    float4 xv = ((const float4*)xin)[idx];
    const float inv = 1.0f / (float)N_NODES;
    float4 o;
    { float mu = s.x * inv, var = sq.x * inv - mu * mu, r = rsqrtf(var + BN_EPSF);
      o.x = xv.x + fmaxf(g.x * (h.x - mu) * r + be.x, 0.f); }
    { float mu = s.y * inv, var = sq.y * inv - mu * mu, r = rsqrtf(var + BN_EPSF);
      o.y = xv.y + fmaxf(g.y * (h.y - mu) * r + be.y, 0.f); }
    { float mu = s.z * inv, var = sq.z * inv - mu * mu, r = rsqrtf(var + BN_EPSF);
      o.z = xv.z + fmaxf(g.z * (h.z - mu) * r + be.z, 0.f); }
    { float mu = s.w * inv, var = sq.w * inv - mu * mu, r = rsqrtf(var + BN_EPSF);
      o.w = xv.w + fmaxf(g.w * (h.w - mu) * r + be.w, 0.f); }
    ((float4*)xout)[idx] = o;
}

// ---------------- launch ----------------
extern "C" void kernel_launch(void* const* d_in, const int* in_sizes, int n_in,
                              void* d_out, int out_size) {
    const float* x     = (const float*)d_in[0];
    const void*  eiraw = d_in[1];
    const float* ew    = (const float*)d_in[3];
    const float* W1    = (const float*)d_in[4];
    const float* b1    = (const float*)d_in[5];
    const float* W2    = (const float*)d_in[6];
    const float* b2    = (const float*)d_in[7];
    const float* eps   = (const float*)d_in[8];
    const float* gamma = (const float*)d_in[9];
    const float* beta  = (const float*)d_in[10];
    float* out = (float*)d_out;

    cudaFuncSetAttribute(k_mlp, cudaFuncAttributeMaxDynamicSharedMemorySize, SMEM_TOT);

    float* gx = nullptr;
    cudaGetSymbolAddress((void**)&gx, g_x);

    k_init<<<7 + (N_NODES + 255) / 256, 256>>>(W1, W2, (const long long*)eiraw);
    k_hist<<<(N_EDGES / 4 + 255) / 256, 256>>>(eiraw);
    k_scan1<<<49, 1024>>>();
    k_scan3<<<49, 1024>>>();
    k_scatter<<<(N_EDGES + 255) / 256, 256>>>(eiraw, ew);

    const int n_mlp_blk = (N_NODES + TM - 1) / TM;
    const float* xin = x;
    for (int l = 0; l < NL; l++) {
        k_agg<<<(N_NODES + 7) / 8, 256>>>(xin);
        k_mlp<<<n_mlp_blk, 256, SMEM_TOT>>>(xin, b1, b2, eps, l);
        float* xout = (l == NL - 1) ? out : gx;
        k_bn<<<(N_NODES * D / 4 + 255) / 256, 256>>>(xin, xout, gamma, beta, l);
        xin = xout;
    }
}

// round 15
// speedup vs baseline: 1.0634x; 1.0634x over previous
#include <cuda_runtime.h>
#include <cuda_bf16.h>
#include <cstdint>

#define N_NODES 50000
#define N_EDGES 800000
#define D 128
#define NL 3
#define BN_EPSF 1e-5f

// ---------------- scratch (device globals; no allocs allowed) ----------------
__device__ __align__(16) float g_agg[N_NODES * D];
__device__ __align__(16) float g_x[N_NODES * D];
__device__ __align__(16) float g_h[N_NODES * D];
__device__ __align__(16) int   g_off[N_NODES + 4];
__device__ __align__(16) int   g_cur[N_NODES];
__device__ __align__(16) int   g_srcs[N_EDGES];
__device__ __align__(16) float g_ws[N_EDGES];
__device__ __align__(16) float g_stats[NL * 2 * D];      // per-layer [sum|sumsq]
__device__ __align__(16) int   g_bsum[64];
__device__ __align__(16) float g_wt[NL * 2 * D * D];     // W^T, tf32-rounded fp32
__device__ int g_is32;

__device__ __forceinline__ uint32_t f2tf32(float v) {
    uint32_t r;
    asm("cvt.rna.tf32.f32 %0, %1;" : "=r"(r) : "f"(v));
    return r;
}

// ---------------- init: weight pre-round (tf32, transposed) + detect + zeros ----
__global__ void k_init(const float* __restrict__ W1, const float* __restrict__ W2,
                       const long long* __restrict__ ei) {
    int b = blockIdx.x, tid = threadIdx.x;
    if (b < 6) {                       // W^T tf32: wt[b][n][k] = rna(W[k][n])
        int l = b >> 1, m = b & 1;
        const float* W = (m ? W2 : W1) + l * D * D;
        float* wt = g_wt + b * D * D;
        for (int idx = tid; idx < D * D; idx += 256) {
            int k = idx >> 7, n = idx & 127;
            wt[n * D + k] = __uint_as_float(f2tf32(W[idx]));
        }
    } else if (b == 6) {               // dtype sniff + BN stats zero
        if (tid == 0) {
            int is32 = 0;
            for (int i = 0; i < 64; i++) {
                long long v = ei[i];
                if (v < 0 || v >= N_NODES) { is32 = 1; break; }
            }
            g_is32 = is32;
        }
        for (int s = tid; s < NL * 2 * D; s += 256) g_stats[s] = 0.f;
    } else {                           // zero degree counters
        int i = (b - 7) * 256 + tid;
        if (i < N_NODES) g_cur[i] = 0;
    }
}

// ---------------- CSR build ----------------
// hist: 4 edges per thread, vectorized loads
__global__ void k_hist(const void* __restrict__ eiraw) {
    int e0 = (blockIdx.x * blockDim.x + threadIdx.x) * 4;
    if (e0 >= N_EDGES) return;
    int d4[4];
    if (g_is32) {
        int4 v = *(const int4*)((const int*)eiraw + N_EDGES + e0);
        d4[0] = v.x; d4[1] = v.y; d4[2] = v.z; d4[3] = v.w;
    } else {
        const long long* p = (const long long*)eiraw + N_EDGES + e0;
        longlong2 v0 = *(const longlong2*)p;
        longlong2 v1 = *(const longlong2*)(p + 2);
        d4[0] = (int)v0.x; d4[1] = (int)v0.y; d4[2] = (int)v1.x; d4[3] = (int)v1.y;
    }
#pragma unroll
    for (int u = 0; u < 4; u++)
        if ((unsigned)d4[u] < N_NODES) atomicAdd(&g_cur[d4[u]], 1);
}

// warp-shuffle block scan (1024 threads, 32 warps)
__global__ void k_scan1() {
    __shared__ int wsum[32];
    int b = blockIdx.x, tid = threadIdx.x;
    int lane = tid & 31, wrp = tid >> 5;
    int i = b * 1024 + tid;
    int v = (i < N_NODES) ? g_cur[i] : 0;
    int x = v;
#pragma unroll
    for (int d = 1; d < 32; d <<= 1) {
        int t = __shfl_up_sync(0xFFFFFFFF, x, d);
        if (lane >= d) x += t;
    }
    if (lane == 31) wsum[wrp] = x;
    __syncthreads();
    if (wrp == 0) {
        int y = wsum[lane];
#pragma unroll
        for (int d = 1; d < 32; d <<= 1) {
            int t = __shfl_up_sync(0xFFFFFFFF, y, d);
            if (lane >= d) y += t;
        }
        wsum[lane] = y;
    }
    __syncthreads();
    int incl = x + (wrp > 0 ? wsum[wrp - 1] : 0);
    if (i < N_NODES) g_off[i] = incl - v;    // block-local exclusive
    if (tid == 1023) g_bsum[b] = incl;
}

// fused cross-block prefix + fixup
__global__ void k_scan3() {
    __shared__ int pre;
    if (threadIdx.x == 0) {
        int acc = 0;
        for (int b = 0; b < blockIdx.x; b++) acc += g_bsum[b];
        pre = acc;
        if (blockIdx.x == 48) g_off[N_NODES] = acc + g_bsum[48];
    }
    __syncthreads();
    int i = blockIdx.x * 1024 + threadIdx.x;
    if (i < N_NODES) {
        int o = g_off[i] + pre;
        g_off[i] = o;
        g_cur[i] = o;
    }
}

// scatter: 4 edges per thread, vectorized loads
__global__ void k_scatter(const void* __restrict__ eiraw, const float* __restrict__ ew) {
    int e0 = (blockIdx.x * blockDim.x + threadIdx.x) * 4;
    if (e0 >= N_EDGES) return;
    int s4[4], d4[4];
    if (g_is32) {
        const int* p = (const int*)eiraw;
        int4 sv = *(const int4*)(p + e0);
        int4 dv = *(const int4*)(p + N_EDGES + e0);
        s4[0] = sv.x; s4[1] = sv.y; s4[2] = sv.z; s4[3] = sv.w;
        d4[0] = dv.x; d4[1] = dv.y; d4[2] = dv.z; d4[3] = dv.w;
    } else {
        const long long* p = (const long long*)eiraw;
        longlong2 s0 = *(const longlong2*)(p + e0);
        longlong2 s1 = *(const longlong2*)(p + e0 + 2);
        longlong2 t0 = *(const longlong2*)(p + N_EDGES + e0);
        longlong2 t1 = *(const longlong2*)(p + N_EDGES + e0 + 2);
        s4[0] = (int)s0.x; s4[1] = (int)s0.y; s4[2] = (int)s1.x; s4[3] = (int)s1.y;
        d4[0] = (int)t0.x; d4[1] = (int)t0.y; d4[2] = (int)t1.x; d4[3] = (int)t1.y;
    }
    float4 wv = *(const float4*)(ew + e0);
    float w4[4] = {wv.x, wv.y, wv.z, wv.w};
#pragma unroll
    for (int u = 0; u < 4; u++) {
        if ((unsigned)s4[u] >= N_NODES || (unsigned)d4[u] >= N_NODES) continue;
        int q = atomicAdd(&g_cur[d4[u]], 1);
        g_srcs[q] = s4[u];
        g_ws[q] = w4[u];
    }
}

// ---------------- aggregation: one warp per node, 8 gathers in flight ----------
__global__ __launch_bounds__(256) void k_agg(const float* __restrict__ xin) {
    int warp = (blockIdx.x * blockDim.x + threadIdx.x) >> 5;
    int lane = threadIdx.x & 31;
    if (warp >= N_NODES) return;
    int beg = g_off[warp];
    int end = g_off[warp + 1];
    float4 acc = make_float4(0.f, 0.f, 0.f, 0.f);
    const float4* xr = (const float4*)xin;
    int j = beg;
    for (; j + 8 <= end; j += 8) {
        int   s[8];
        float w[8];
#pragma unroll
        for (int u = 0; u < 8; u++) { s[u] = g_srcs[j + u]; w[u] = g_ws[j + u]; }
        float4 v[8];
#pragma unroll
        for (int u = 0; u < 8; u++) v[u] = xr[s[u] * (D / 4) + lane];
#pragma unroll
        for (int u = 0; u < 8; u++) {
            acc.x += w[u] * v[u].x;
            acc.y += w[u] * v[u].y;
            acc.z += w[u] * v[u].z;
            acc.w += w[u] * v[u].w;
        }
    }
    for (; j + 2 <= end; j += 2) {
        int s0 = g_srcs[j];     float w0 = g_ws[j];
        int s1 = g_srcs[j + 1]; float w1 = g_ws[j + 1];
        float4 v0 = xr[s0 * (D / 4) + lane];
        float4 v1 = xr[s1 * (D / 4) + lane];
        acc.x += w0 * v0.x + w1 * v1.x;
        acc.y += w0 * v0.y + w1 * v1.y;
        acc.z += w0 * v0.z + w1 * v1.z;
        acc.w += w0 * v0.w + w1 * v1.w;
    }
    if (j < end) {
        int s0 = g_srcs[j]; float w0 = g_ws[j];
        float4 v0 = xr[s0 * (D / 4) + lane];
        acc.x += w0 * v0.x; acc.y += w0 * v0.y;
        acc.z += w0 * v0.z; acc.w += w0 * v0.w;
    }
    ((float4*)g_agg)[warp * (D / 4) + lane] = acc;
}

// ---------------- single-pass tf32 mma.sync fused MLP ----------------
// 512 threads, 4x4 warp grid (warp tile 32x32), 128-row tile, 1 CTA/SM.
// smem: sA [128][132] fp32 @ 0, sB [128][132] fp32 @ 67584.
// sT (128x129 f32) aliases sB; BN-reduce arrays alias sA.
#define SROW 132
#define OFF_A 0
#define OFF_B 67584
#define SMEM_TOT 135168

__device__ __forceinline__ void mma_tf32(float* d, const uint32_t* a,
                                         uint32_t b0, uint32_t b1) {
    asm volatile(
        "mma.sync.aligned.m16n8k8.row.col.f32.tf32.tf32.f32 "
        "{%0,%1,%2,%3}, {%4,%5,%6,%7}, {%8,%9}, {%0,%1,%2,%3};"
        : "+f"(d[0]), "+f"(d[1]), "+f"(d[2]), "+f"(d[3])
        : "r"(a[0]), "r"(a[1]), "r"(a[2]), "r"(a[3]), "r"(b0), "r"(b1));
}

// 128x128x128 GEMM, single tf32 pass, into d[2][4][4]; warp tile 32x32
__device__ __forceinline__ void gemm_tf32(const char* sm, float d[2][4][4],
                                          int rbase, int cbase, int lane) {
    int gr = lane >> 2;
    int tg = lane & 3;
    const uint32_t* A = (const uint32_t*)(sm + OFF_A);
    const uint32_t* B = (const uint32_t*)(sm + OFF_B);
#pragma unroll
    for (int k0 = 0; k0 < 16; k0++) {
        int kc = k0 * 8;
        uint32_t a[2][4];
#pragma unroll
        for (int mf = 0; mf < 2; mf++) {
            int r0 = rbase + mf * 16 + gr;
            a[mf][0] = A[r0 * SROW + kc + tg];
            a[mf][1] = A[(r0 + 8) * SROW + kc + tg];
            a[mf][2] = A[r0 * SROW + kc + tg + 4];
            a[mf][3] = A[(r0 + 8) * SROW + kc + tg + 4];
        }
#pragma unroll
        for (int nf = 0; nf < 4; nf++) {
            int n0 = cbase + nf * 8 + gr;
            uint32_t b0 = B[n0 * SROW + kc + tg];
            uint32_t b1 = B[n0 * SROW + kc + tg + 4];
            mma_tf32(d[0][nf], a[0], b0, b1);
            mma_tf32(d[1][nf], a[1], b0, b1);
        }
    }
}

__global__ __launch_bounds__(512, 1) void k_mlp(
    const float* __restrict__ xin,
    const float* __restrict__ b1, const float* __restrict__ b2,
    const float* __restrict__ epsv, int layer) {
    extern __shared__ char sm[];
    int tid = threadIdx.x, lane = tid & 31, wid = tid >> 5;
    int m0 = blockIdx.x * 128;
    int wm = wid >> 2, wn = wid & 3;          // 4 x 4 warp grid
    int rbase = wm * 32, cbase = wn * 32;
    int gr = lane >> 2, tg2 = (lane & 3) * 2;

    float* sA = (float*)(sm + OFF_A);
    float* sB = (float*)(sm + OFF_B);

    // ---- stage A = tf32((1+eps)*x + agg), zero OOB rows ----
    float e1 = 1.0f + epsv[layer];
    for (int idx = tid * 4; idx < D * D; idx += 2048) {
        int r = idx >> 7, c = idx & 127;
        int gro = m0 + r;
        float4 v = make_float4(0.f, 0.f, 0.f, 0.f);
        if (gro < N_NODES) {
            float4 xv = *(const float4*)(xin + gro * D + c);
            float4 av = *(const float4*)(g_agg + gro * D + c);
            v.x = e1 * xv.x + av.x; v.y = e1 * xv.y + av.y;
            v.z = e1 * xv.z + av.z; v.w = e1 * xv.w + av.w;
        }
        float4 t;
        t.x = __uint_as_float(f2tf32(v.x));
        t.y = __uint_as_float(f2tf32(v.y));
        t.z = __uint_as_float(f2tf32(v.z));
        t.w = __uint_as_float(f2tf32(v.w));
        *(float4*)&sA[r * SROW + c] = t;
    }
    // ---- stage W1^T (already tf32-rounded; pure copy) ----
    {
        const float* wt = g_wt + (layer * 2 + 0) * D * D;
        for (int idx = tid * 4; idx < D * D; idx += 2048) {
            int n = idx >> 7, k = idx & 127;
            *(float4*)&sB[n * SROW + k] = *(const float4*)&wt[idx];
        }
    }
    __syncthreads();

    // ---- GEMM1: H1 = A @ W1 ----
    float d[2][4][4];
#pragma unroll
    for (int mf = 0; mf < 2; mf++)
#pragma unroll
        for (int nf = 0; nf < 4; nf++)
#pragma unroll
            for (int q = 0; q < 4; q++) d[mf][nf][q] = 0.f;
    gemm_tf32(sm, d, rbase, cbase, lane);
    __syncthreads();

    // ---- epilogue1: tf32(relu(H1 + b1)) -> back into sA ----
    {
        const float* bb = b1 + layer * D;
#pragma unroll
        for (int mf = 0; mf < 2; mf++) {
            int r0 = rbase + mf * 16 + gr;
#pragma unroll
            for (int nf = 0; nf < 4; nf++) {
                int col = cbase + nf * 8 + tg2;
                float bv0 = bb[col], bv1 = bb[col + 1];
                sA[r0 * SROW + col]           = __uint_as_float(f2tf32(fmaxf(d[mf][nf][0] + bv0, 0.f)));
                sA[r0 * SROW + col + 1]       = __uint_as_float(f2tf32(fmaxf(d[mf][nf][1] + bv1, 0.f)));
                sA[(r0 + 8) * SROW + col]     = __uint_as_float(f2tf32(fmaxf(d[mf][nf][2] + bv0, 0.f)));
                sA[(r0 + 8) * SROW + col + 1] = __uint_as_float(f2tf32(fmaxf(d[mf][nf][3] + bv1, 0.f)));
            }
        }
    }
    // ---- stage W2^T ----
    {
        const float* wt = g_wt + (layer * 2 + 1) * D * D;
        for (int idx = tid * 4; idx < D * D; idx += 2048) {
            int n = idx >> 7, k = idx & 127;
            *(float4*)&sB[n * SROW + k] = *(const float4*)&wt[idx];
        }
    }
    __syncthreads();

    // ---- GEMM2: H2 = relu(H1) @ W2 ----
#pragma unroll
    for (int mf = 0; mf < 2; mf++)
#pragma unroll
        for (int nf = 0; nf < 4; nf++)
#pragma unroll
            for (int q = 0; q < 4; q++) d[mf][nf][q] = 0.f;
    gemm_tf32(sm, d, rbase, cbase, lane);
    __syncthreads();

    // ---- epilogue2: h = H2 + b2 -> sT (zero OOB rows) ----
    float* sT = (float*)(sm + OFF_B);   // 128 x 129 floats = 66048B <= 67584B
    {
        const float* bb = b2 + layer * D;
#pragma unroll
        for (int mf = 0; mf < 2; mf++) {
            int r0 = rbase + mf * 16 + gr;
            bool v0ok = (m0 + r0) < N_NODES;
            bool v1ok = (m0 + r0 + 8) < N_NODES;
#pragma unroll
            for (int nf = 0; nf < 4; nf++) {
                int col = cbase + nf * 8 + tg2;
                float bv0 = bb[col], bv1 = bb[col + 1];
                sT[r0 * 129 + col]           = v0ok ? d[mf][nf][0] + bv0 : 0.f;
                sT[r0 * 129 + col + 1]       = v0ok ? d[mf][nf][1] + bv1 : 0.f;
                sT[(r0 + 8) * 129 + col]     = v1ok ? d[mf][nf][2] + bv0 : 0.f;
                sT[(r0 + 8) * 129 + col + 1] = v1ok ? d[mf][nf][3] + bv1 : 0.f;
            }
        }
    }
    __syncthreads();

    // ---- BN column partial sums: 4 row-quarters per column (alias sA) ----
    float* sRedS = (float*)(sm + OFF_A);         // 512 floats
    float* sRedQ = (float*)(sm + OFF_A) + 512;   // 512 floats
    {
        int col = tid & 127, rq = tid >> 7;
        float s = 0.f, q = 0.f;
        int rlo = rq * 32;
#pragma unroll 4
        for (int r = rlo; r < rlo + 32; r++) {
            float h = sT[r * 129 + col];
            s += h; q += h * h;
        }
        sRedS[rq * 128 + col] = s;
        sRedQ[rq * 128 + col] = q;
    }
    __syncthreads();
    float* stats = g_stats + layer * 2 * D;
    if (tid < 128) {
        atomicAdd(&stats[tid],
                  sRedS[tid] + sRedS[128 + tid] + sRedS[256 + tid] + sRedS[384 + tid]);
    } else if (tid < 256) {
        int c = tid - 128;
        atomicAdd(&stats[128 + c],
                  sRedQ[c] + sRedQ[128 + c] + sRedQ[256 + c] + sRedQ[384 + c]);
    }
    // ---- coalesced g_h store ----
    for (int idx = tid; idx < 4096; idx += 512) {
        int r = idx >> 5, c4 = (idx & 31) << 2;
        int gro = m0 + r;
        if (gro < N_NODES) {
            float4 o = make_float4(sT[r * 129 + c4], sT[r * 129 + c4 + 1],
                                   sT[r * 129 + c4 + 2], sT[r * 129 + c4 + 3]);
            *(float4*)(g_h + gro * D + c4) = o;
        }
    }
}

// ---------------- BN apply + relu + residual ----------------
__global__ void k_bn(const float* __restrict__ xin, float* __restrict__ xout,
                     const float* __restrict__ gamma, const float* __restrict__ beta,
                     int layer) {
    int idx = blockIdx.x * blockDim.x + threadIdx.x;
    if (idx >= N_NODES * D / 4) return;
    int c = (idx & 31) * 4;
    const float* stats = g_stats + layer * 2 * D;
    float4 s  = *(const float4*)(stats + c);
    float4 sq = *(const float4*)(stats + D + c);
    float4 g  = *(const float4*)(gamma + layer * D + c);
    float4 be = *(const float4*)(beta + layer * D + c);
    float4 h  = ((const float4*)g_h)[idx];
    float4 xv = ((const float4*)xin)[idx];
    const float inv = 1.0f / (float)N_NODES;
    float4 o;
    { float mu = s.x * inv, var = sq.x * inv - mu * mu, r = rsqrtf(var + BN_EPSF);
      o.x = xv.x + fmaxf(g.x * (h.x - mu) * r + be.x, 0.f); }
    { float mu = s.y * inv, var = sq.y * inv - mu * mu, r = rsqrtf(var + BN_EPSF);
      o.y = xv.y + fmaxf(g.y * (h.y - mu) * r + be.y, 0.f); }
    { float mu = s.z * inv, var = sq.z * inv - mu * mu, r = rsqrtf(var + BN_EPSF);
      o.z = xv.z + fmaxf(g.z * (h.z - mu) * r + be.z, 0.f); }
    { float mu = s.w * inv, var = sq.w * inv - mu * mu, r = rsqrtf(var + BN_EPSF);
      o.w = xv.w + fmaxf(g.w * (h.w - mu) * r + be.w, 0.f); }
    ((float4*)xout)[idx] = o;
}

// ---------------- launch ----------------
extern "C" void kernel_launch(void* const* d_in, const int* in_sizes, int n_in,
                              void* d_out, int out_size) {
    const float* x     = (const float*)d_in[0];
    const void*  eiraw = d_in[1];
    const float* ew    = (const float*)d_in[3];
    const float* W1    = (const float*)d_in[4];
    const float* b1    = (const float*)d_in[5];
    const float* W2    = (const float*)d_in[6];
    const float* b2    = (const float*)d_in[7];
    const float* eps   = (const float*)d_in[8];
    const float* gamma = (const float*)d_in[9];
    const float* beta  = (const float*)d_in[10];
    float* out = (float*)d_out;

    cudaFuncSetAttribute(k_mlp, cudaFuncAttributeMaxDynamicSharedMemorySize, SMEM_TOT);

    float* gx = nullptr;
    cudaGetSymbolAddress((void**)&gx, g_x);

    k_init<<<7 + (N_NODES + 255) / 256, 256>>>(W1, W2, (const long long*)eiraw);
    k_hist<<<(N_EDGES / 4 + 255) / 256, 256>>>(eiraw);
    k_scan1<<<49, 1024>>>();
    k_scan3<<<49, 1024>>>();
    k_scatter<<<(N_EDGES / 4 + 255) / 256, 256>>>(eiraw, ew);

    const int n_mlp_blk = (N_NODES + 127) / 128;
    const float* xin = x;
    for (int l = 0; l < NL; l++) {
        k_agg<<<(N_NODES + 7) / 8, 256>>>(xin);
        k_mlp<<<n_mlp_blk, 512, SMEM_TOT>>>(xin, b1, b2, eps, l);
        float* xout = (l == NL - 1) ? out : gx;
        k_bn<<<(N_NODES * D / 4 + 255) / 256, 256>>>(xin, xout, gamma, beta, l);
        xin = xout;
    }
}

// round 16
// speedup vs baseline: 1.0793x; 1.0150x over previous
#include <cuda_runtime.h>
#include <cuda_bf16.h>
#include <cstdint>

#define N_NODES 50000
#define N_EDGES 800000
#define D 128
#define NL 3
#define BN_EPSF 1e-5f

// ---------------- scratch (device globals; no allocs allowed) ----------------
__device__ __align__(16) float g_agg[N_NODES * D];   // holds A = tf32((1+eps)x+agg)
__device__ __align__(16) float g_x[N_NODES * D];
__device__ __align__(16) float g_h[N_NODES * D];
__device__ __align__(16) int   g_off[N_NODES + 4];
__device__ __align__(16) int   g_cur[N_NODES];
__device__ __align__(16) int   g_srcs[N_EDGES];
__device__ __align__(16) float g_ws[N_EDGES];
__device__ __align__(16) float g_stats[NL * 2 * D];      // per-layer [sum|sumsq]
__device__ __align__(16) int   g_bsum[64];
__device__ __align__(16) float g_wt[NL * 2 * D * D];     // W^T, tf32-rounded fp32
__device__ int g_is32;

__device__ __forceinline__ uint32_t f2tf32(float v) {
    uint32_t r;
    asm("cvt.rna.tf32.f32 %0, %1;" : "=r"(r) : "f"(v));
    return r;
}

// ---------------- init: weight pre-round (tf32, transposed) + detect + zeros ----
__global__ void k_init(const float* __restrict__ W1, const float* __restrict__ W2,
                       const long long* __restrict__ ei) {
    int b = blockIdx.x, tid = threadIdx.x;
    if (b < 6) {                       // W^T tf32: wt[b][n][k] = rna(W[k][n])
        int l = b >> 1, m = b & 1;
        const float* W = (m ? W2 : W1) + l * D * D;
        float* wt = g_wt + b * D * D;
        for (int idx = tid; idx < D * D; idx += 256) {
            int k = idx >> 7, n = idx & 127;
            wt[n * D + k] = __uint_as_float(f2tf32(W[idx]));
        }
    } else if (b == 6) {               // dtype sniff + BN stats zero
        if (tid == 0) {
            int is32 = 0;
            for (int i = 0; i < 64; i++) {
                long long v = ei[i];
                if (v < 0 || v >= N_NODES) { is32 = 1; break; }
            }
            g_is32 = is32;
        }
        for (int s = tid; s < NL * 2 * D; s += 256) g_stats[s] = 0.f;
    } else {                           // zero degree counters
        int i = (b - 7) * 256 + tid;
        if (i < N_NODES) g_cur[i] = 0;
    }
}

// ---------------- CSR build ----------------
// hist: 4 edges per thread, vectorized loads
__global__ void k_hist(const void* __restrict__ eiraw) {
    int e0 = (blockIdx.x * blockDim.x + threadIdx.x) * 4;
    if (e0 >= N_EDGES) return;
    int d4[4];
    if (g_is32) {
        int4 v = *(const int4*)((const int*)eiraw + N_EDGES + e0);
        d4[0] = v.x; d4[1] = v.y; d4[2] = v.z; d4[3] = v.w;
    } else {
        const long long* p = (const long long*)eiraw + N_EDGES + e0;
        longlong2 v0 = *(const longlong2*)p;
        longlong2 v1 = *(const longlong2*)(p + 2);
        d4[0] = (int)v0.x; d4[1] = (int)v0.y; d4[2] = (int)v1.x; d4[3] = (int)v1.y;
    }
#pragma unroll
    for (int u = 0; u < 4; u++)
        if ((unsigned)d4[u] < N_NODES) atomicAdd(&g_cur[d4[u]], 1);
}

// warp-shuffle block scan (1024 threads, 32 warps)
__global__ void k_scan1() {
    __shared__ int wsum[32];
    int b = blockIdx.x, tid = threadIdx.x;
    int lane = tid & 31, wrp = tid >> 5;
    int i = b * 1024 + tid;
    int v = (i < N_NODES) ? g_cur[i] : 0;
    int x = v;
#pragma unroll
    for (int d = 1; d < 32; d <<= 1) {
        int t = __shfl_up_sync(0xFFFFFFFF, x, d);
        if (lane >= d) x += t;
    }
    if (lane == 31) wsum[wrp] = x;
    __syncthreads();
    if (wrp == 0) {
        int y = wsum[lane];
#pragma unroll
        for (int d = 1; d < 32; d <<= 1) {
            int t = __shfl_up_sync(0xFFFFFFFF, y, d);
            if (lane >= d) y += t;
        }
        wsum[lane] = y;
    }
    __syncthreads();
    int incl = x + (wrp > 0 ? wsum[wrp - 1] : 0);
    if (i < N_NODES) g_off[i] = incl - v;    // block-local exclusive
    if (tid == 1023) g_bsum[b] = incl;
}

// fused cross-block prefix + fixup
__global__ void k_scan3() {
    __shared__ int pre;
    if (threadIdx.x == 0) {
        int acc = 0;
        for (int b = 0; b < blockIdx.x; b++) acc += g_bsum[b];
        pre = acc;
        if (blockIdx.x == 48) g_off[N_NODES] = acc + g_bsum[48];
    }
    __syncthreads();
    int i = blockIdx.x * 1024 + threadIdx.x;
    if (i < N_NODES) {
        int o = g_off[i] + pre;
        g_off[i] = o;
        g_cur[i] = o;
    }
}

// scatter: 4 edges per thread, vectorized loads
__global__ void k_scatter(const void* __restrict__ eiraw, const float* __restrict__ ew) {
    int e0 = (blockIdx.x * blockDim.x + threadIdx.x) * 4;
    if (e0 >= N_EDGES) return;
    int s4[4], d4[4];
    if (g_is32) {
        const int* p = (const int*)eiraw;
        int4 sv = *(const int4*)(p + e0);
        int4 dv = *(const int4*)(p + N_EDGES + e0);
        s4[0] = sv.x; s4[1] = sv.y; s4[2] = sv.z; s4[3] = sv.w;
        d4[0] = dv.x; d4[1] = dv.y; d4[2] = dv.z; d4[3] = dv.w;
    } else {
        const long long* p = (const long long*)eiraw;
        longlong2 s0 = *(const longlong2*)(p + e0);
        longlong2 s1 = *(const longlong2*)(p + e0 + 2);
        longlong2 t0 = *(const longlong2*)(p + N_EDGES + e0);
        longlong2 t1 = *(const longlong2*)(p + N_EDGES + e0 + 2);
        s4[0] = (int)s0.x; s4[1] = (int)s0.y; s4[2] = (int)s1.x; s4[3] = (int)s1.y;
        d4[0] = (int)t0.x; d4[1] = (int)t0.y; d4[2] = (int)t1.x; d4[3] = (int)t1.y;
    }
    float4 wv = *(const float4*)(ew + e0);
    float w4[4] = {wv.x, wv.y, wv.z, wv.w};
#pragma unroll
    for (int u = 0; u < 4; u++) {
        if ((unsigned)s4[u] >= N_NODES || (unsigned)d4[u] >= N_NODES) continue;
        int q = atomicAdd(&g_cur[d4[u]], 1);
        g_srcs[q] = s4[u];
        g_ws[q] = w4[u];
    }
}

// ---------------- aggregation + GIN-combine fused ----------------
// one warp per node, 8 gathers in flight; writes A = tf32((1+eps)*x + agg)
__global__ __launch_bounds__(256) void k_agg(const float* __restrict__ xin,
                                             const float* __restrict__ epsv, int layer) {
    int warp = (blockIdx.x * blockDim.x + threadIdx.x) >> 5;
    int lane = threadIdx.x & 31;
    if (warp >= N_NODES) return;
    int beg = g_off[warp];
    int end = g_off[warp + 1];
    float4 acc = make_float4(0.f, 0.f, 0.f, 0.f);
    const float4* xr = (const float4*)xin;
    int j = beg;
    for (; j + 8 <= end; j += 8) {
        int   s[8];
        float w[8];
#pragma unroll
        for (int u = 0; u < 8; u++) { s[u] = g_srcs[j + u]; w[u] = g_ws[j + u]; }
        float4 v[8];
#pragma unroll
        for (int u = 0; u < 8; u++) v[u] = xr[s[u] * (D / 4) + lane];
#pragma unroll
        for (int u = 0; u < 8; u++) {
            acc.x += w[u] * v[u].x;
            acc.y += w[u] * v[u].y;
            acc.z += w[u] * v[u].z;
            acc.w += w[u] * v[u].w;
        }
    }
    for (; j + 2 <= end; j += 2) {
        int s0 = g_srcs[j];     float w0 = g_ws[j];
        int s1 = g_srcs[j + 1]; float w1 = g_ws[j + 1];
        float4 v0 = xr[s0 * (D / 4) + lane];
        float4 v1 = xr[s1 * (D / 4) + lane];
        acc.x += w0 * v0.x + w1 * v1.x;
        acc.y += w0 * v0.y + w1 * v1.y;
        acc.z += w0 * v0.z + w1 * v1.z;
        acc.w += w0 * v0.w + w1 * v1.w;
    }
    if (j < end) {
        int s0 = g_srcs[j]; float w0 = g_ws[j];
        float4 v0 = xr[s0 * (D / 4) + lane];
        acc.x += w0 * v0.x; acc.y += w0 * v0.y;
        acc.z += w0 * v0.z; acc.w += w0 * v0.w;
    }
    // fuse GIN combine: A = tf32((1+eps)*x[node] + agg)
    float e1 = 1.0f + epsv[layer];
    float4 xv = xr[warp * (D / 4) + lane];
    float4 t;
    t.x = __uint_as_float(f2tf32(e1 * xv.x + acc.x));
    t.y = __uint_as_float(f2tf32(e1 * xv.y + acc.y));
    t.z = __uint_as_float(f2tf32(e1 * xv.z + acc.z));
    t.w = __uint_as_float(f2tf32(e1 * xv.w + acc.w));
    ((float4*)g_agg)[warp * (D / 4) + lane] = t;
}

// ---------------- single-pass tf32 mma.sync fused MLP ----------------
// 512 threads, 4x4 warp grid (warp tile 32x32), 128-row tile, 1 CTA/SM.
// smem: sA [128][132] fp32 @ 0, sB [128][132] fp32 @ 67584.
// sT (128x129 f32) aliases sB; BN-reduce arrays alias sA.
#define SROW 132
#define OFF_A 0
#define OFF_B 67584
#define SMEM_TOT 135168

__device__ __forceinline__ void mma_tf32(float* d, const uint32_t* a,
                                         uint32_t b0, uint32_t b1) {
    asm volatile(
        "mma.sync.aligned.m16n8k8.row.col.f32.tf32.tf32.f32 "
        "{%0,%1,%2,%3}, {%4,%5,%6,%7}, {%8,%9}, {%0,%1,%2,%3};"
        : "+f"(d[0]), "+f"(d[1]), "+f"(d[2]), "+f"(d[3])
        : "r"(a[0]), "r"(a[1]), "r"(a[2]), "r"(a[3]), "r"(b0), "r"(b1));
}

// 128x128x128 GEMM, single tf32 pass, into d[2][4][4]; warp tile 32x32
__device__ __forceinline__ void gemm_tf32(const char* sm, float d[2][4][4],
                                          int rbase, int cbase, int lane) {
    int gr = lane >> 2;
    int tg = lane & 3;
    const uint32_t* A = (const uint32_t*)(sm + OFF_A);
    const uint32_t* B = (const uint32_t*)(sm + OFF_B);
#pragma unroll
    for (int k0 = 0; k0 < 16; k0++) {
        int kc = k0 * 8;
        uint32_t a[2][4];
#pragma unroll
        for (int mf = 0; mf < 2; mf++) {
            int r0 = rbase + mf * 16 + gr;
            a[mf][0] = A[r0 * SROW + kc + tg];
            a[mf][1] = A[(r0 + 8) * SROW + kc + tg];
            a[mf][2] = A[r0 * SROW + kc + tg + 4];
            a[mf][3] = A[(r0 + 8) * SROW + kc + tg + 4];
        }
#pragma unroll
        for (int nf = 0; nf < 4; nf++) {
            int n0 = cbase + nf * 8 + gr;
            uint32_t b0 = B[n0 * SROW + kc + tg];
            uint32_t b1 = B[n0 * SROW + kc + tg + 4];
            mma_tf32(d[0][nf], a[0], b0, b1);
            mma_tf32(d[1][nf], a[1], b0, b1);
        }
    }
}

__global__ __launch_bounds__(512, 1) void k_mlp(
    const float* __restrict__ b1, const float* __restrict__ b2, int layer) {
    extern __shared__ char sm[];
    int tid = threadIdx.x, lane = tid & 31, wid = tid >> 5;
    int m0 = blockIdx.x * 128;
    int wm = wid >> 2, wn = wid & 3;          // 4 x 4 warp grid
    int rbase = wm * 32, cbase = wn * 32;
    int gr = lane >> 2, tg2 = (lane & 3) * 2;

    float* sA = (float*)(sm + OFF_A);
    float* sB = (float*)(sm + OFF_B);

    // ---- stage A: pure copy of pre-fused, pre-rounded g_agg rows ----
    for (int idx = tid * 4; idx < D * D; idx += 2048) {
        int r = idx >> 7, c = idx & 127;
        int gro = m0 + r;
        float4 v = make_float4(0.f, 0.f, 0.f, 0.f);
        if (gro < N_NODES) v = *(const float4*)(g_agg + gro * D + c);
        *(float4*)&sA[r * SROW + c] = v;
    }
    // ---- stage W1^T (already tf32-rounded; pure copy) ----
    {
        const float* wt = g_wt + (layer * 2 + 0) * D * D;
        for (int idx = tid * 4; idx < D * D; idx += 2048) {
            int n = idx >> 7, k = idx & 127;
            *(float4*)&sB[n * SROW + k] = *(const float4*)&wt[idx];
        }
    }
    __syncthreads();

    // ---- GEMM1: H1 = A @ W1 ----
    float d[2][4][4];
#pragma unroll
    for (int mf = 0; mf < 2; mf++)
#pragma unroll
        for (int nf = 0; nf < 4; nf++)
#pragma unroll
            for (int q = 0; q < 4; q++) d[mf][nf][q] = 0.f;
    gemm_tf32(sm, d, rbase, cbase, lane);
    __syncthreads();

    // ---- epilogue1: tf32(relu(H1 + b1)) -> back into sA ----
    {
        const float* bb = b1 + layer * D;
#pragma unroll
        for (int mf = 0; mf < 2; mf++) {
            int r0 = rbase + mf * 16 + gr;
#pragma unroll
            for (int nf = 0; nf < 4; nf++) {
                int col = cbase + nf * 8 + tg2;
                float bv0 = bb[col], bv1 = bb[col + 1];
                sA[r0 * SROW + col]           = __uint_as_float(f2tf32(fmaxf(d[mf][nf][0] + bv0, 0.f)));
                sA[r0 * SROW + col + 1]       = __uint_as_float(f2tf32(fmaxf(d[mf][nf][1] + bv1, 0.f)));
                sA[(r0 + 8) * SROW + col]     = __uint_as_float(f2tf32(fmaxf(d[mf][nf][2] + bv0, 0.f)));
                sA[(r0 + 8) * SROW + col + 1] = __uint_as_float(f2tf32(fmaxf(d[mf][nf][3] + bv1, 0.f)));
            }
        }
    }
    // ---- stage W2^T ----
    {
        const float* wt = g_wt + (layer * 2 + 1) * D * D;
        for (int idx = tid * 4; idx < D * D; idx += 2048) {
            int n = idx >> 7, k = idx & 127;
            *(float4*)&sB[n * SROW + k] = *(const float4*)&wt[idx];
        }
    }
    __syncthreads();

    // ---- GEMM2: H2 = relu(H1) @ W2 ----
#pragma unroll
    for (int mf = 0; mf < 2; mf++)
#pragma unroll
        for (int nf = 0; nf < 4; nf++)
#pragma unroll
            for (int q = 0; q < 4; q++) d[mf][nf][q] = 0.f;
    gemm_tf32(sm, d, rbase, cbase, lane);
    __syncthreads();

    // ---- epilogue2: h = H2 + b2 -> sT (zero OOB rows) ----
    float* sT = (float*)(sm + OFF_B);   // 128 x 129 floats = 66048B <= 67584B
    {
        const float* bb = b2 + layer * D;
#pragma unroll
        for (int mf = 0; mf < 2; mf++) {
            int r0 = rbase + mf * 16 + gr;
            bool v0ok = (m0 + r0) < N_NODES;
            bool v1ok = (m0 + r0 + 8) < N_NODES;
#pragma unroll
            for (int nf = 0; nf < 4; nf++) {
                int col = cbase + nf * 8 + tg2;
                float bv0 = bb[col], bv1 = bb[col + 1];
                sT[r0 * 129 + col]           = v0ok ? d[mf][nf][0] + bv0 : 0.f;
                sT[r0 * 129 + col + 1]       = v0ok ? d[mf][nf][1] + bv1 : 0.f;
                sT[(r0 + 8) * 129 + col]     = v1ok ? d[mf][nf][2] + bv0 : 0.f;
                sT[(r0 + 8) * 129 + col + 1] = v1ok ? d[mf][nf][3] + bv1 : 0.f;
            }
        }
    }
    __syncthreads();

    // ---- BN column partial sums: 4 row-quarters per column (alias sA) ----
    float* sRedS = (float*)(sm + OFF_A);         // 512 floats
    float* sRedQ = (float*)(sm + OFF_A) + 512;   // 512 floats
    {
        int col = tid & 127, rq = tid >> 7;
        float s = 0.f, q = 0.f;
        int rlo = rq * 32;
#pragma unroll 4
        for (int r = rlo; r < rlo + 32; r++) {
            float h = sT[r * 129 + col];
            s += h; q += h * h;
        }
        sRedS[rq * 128 + col] = s;
        sRedQ[rq * 128 + col] = q;
    }
    __syncthreads();
    float* stats = g_stats + layer * 2 * D;
    if (tid < 128) {
        atomicAdd(&stats[tid],
                  sRedS[tid] + sRedS[128 + tid] + sRedS[256 + tid] + sRedS[384 + tid]);
    } else if (tid < 256) {
        int c = tid - 128;
        atomicAdd(&stats[128 + c],
                  sRedQ[c] + sRedQ[128 + c] + sRedQ[256 + c] + sRedQ[384 + c]);
    }
    // ---- coalesced g_h store ----
    for (int idx = tid; idx < 4096; idx += 512) {
        int r = idx >> 5, c4 = (idx & 31) << 2;
        int gro = m0 + r;
        if (gro < N_NODES) {
            float4 o = make_float4(sT[r * 129 + c4], sT[r * 129 + c4 + 1],
                                   sT[r * 129 + c4 + 2], sT[r * 129 + c4 + 3]);
            *(float4*)(g_h + gro * D + c4) = o;
        }
    }
}

// ---------------- BN apply + relu + residual ----------------
__global__ void k_bn(const float* __restrict__ xin, float* __restrict__ xout,
                     const float* __restrict__ gamma, const float* __restrict__ beta,
                     int layer) {
    int idx = blockIdx.x * blockDim.x + threadIdx.x;
    if (idx >= N_NODES * D / 4) return;
    int c = (idx & 31) * 4;
    const float* stats = g_stats + layer * 2 * D;
    float4 s  = *(const float4*)(stats + c);
    float4 sq = *(const float4*)(stats + D + c);
    float4 g  = *(const float4*)(gamma + layer * D + c);
    float4 be = *(const float4*)(beta + layer * D + c);
    float4 h  = ((const float4*)g_h)[idx];
    float4 xv = ((const float4*)xin)[idx];
    const float inv = 1.0f / (float)N_NODES;
    float4 o;
    { float mu = s.x * inv, var = sq.x * inv - mu * mu, r = rsqrtf(var + BN_EPSF);
      o.x = xv.x + fmaxf(g.x * (h.x - mu) * r + be.x, 0.f); }
    { float mu = s.y * inv, var = sq.y * inv - mu * mu, r = rsqrtf(var + BN_EPSF);
      o.y = xv.y + fmaxf(g.y * (h.y - mu) * r + be.y, 0.f); }
    { float mu = s.z * inv, var = sq.z * inv - mu * mu, r = rsqrtf(var + BN_EPSF);
      o.z = xv.z + fmaxf(g.z * (h.z - mu) * r + be.z, 0.f); }
    { float mu = s.w * inv, var = sq.w * inv - mu * mu, r = rsqrtf(var + BN_EPSF);
      o.w = xv.w + fmaxf(g.w * (h.w - mu) * r + be.w, 0.f); }
    ((float4*)xout)[idx] = o;
}

// ---------------- launch ----------------
extern "C" void kernel_launch(void* const* d_in, const int* in_sizes, int n_in,
                              void* d_out, int out_size) {
    const float* x     = (const float*)d_in[0];
    const void*  eiraw = d_in[1];
    const float* ew    = (const float*)d_in[3];
    const float* W1    = (const float*)d_in[4];
    const float* b1    = (const float*)d_in[5];
    const float* W2    = (const float*)d_in[6];
    const float* b2    = (const float*)d_in[7];
    const float* eps   = (const float*)d_in[8];
    const float* gamma = (const float*)d_in[9];
    const float* beta  = (const float*)d_in[10];
    float* out = (float*)d_out;

    cudaFuncSetAttribute(k_mlp, cudaFuncAttributeMaxDynamicSharedMemorySize, SMEM_TOT);

    float* gx = nullptr;
    cudaGetSymbolAddress((void**)&gx, g_x);

    k_init<<<7 + (N_NODES + 255) / 256, 256>>>(W1, W2, (const long long*)eiraw);
    k_hist<<<(N_EDGES / 4 + 255) / 256, 256>>>(eiraw);
    k_scan1<<<49, 1024>>>();
    k_scan3<<<49, 1024>>>();
    k_scatter<<<(N_EDGES / 4 + 255) / 256, 256>>>(eiraw, ew);

    const int n_mlp_blk = (N_NODES + 127) / 128;
    const float* xin = x;
    for (int l = 0; l < NL; l++) {
        k_agg<<<(N_NODES + 7) / 8, 256>>>(xin, eps, l);
        k_mlp<<<n_mlp_blk, 512, SMEM_TOT>>>(b1, b2, l);
        float* xout = (l == NL - 1) ? out : gx;
        k_bn<<<(N_NODES * D / 4 + 255) / 256, 256>>>(xin, xout, gamma, beta, l);
        xin = xout;
    }
}

// round 17
// speedup vs baseline: 1.1364x; 1.0529x over previous
#include <cuda_runtime.h>
#include <cuda_bf16.h>
#include <cstdint>

#define N_NODES 50000
#define N_EDGES 800000
#define D 128
#define NL 3
#define BN_EPSF 1e-5f

// ---------------- scratch (device globals; no allocs allowed) ----------------
__device__ __align__(16) float g_agg[N_NODES * D];   // holds A = tf32((1+eps)x+agg)
__device__ __align__(16) float g_x[N_NODES * D];
__device__ __align__(16) float g_h[N_NODES * D];
__device__ __align__(16) int   g_off[N_NODES + 4];
__device__ __align__(16) int   g_cur[N_NODES];
__device__ __align__(16) int   g_srcs[N_EDGES];
__device__ __align__(16) float g_ws[N_EDGES];
__device__ __align__(16) float g_stats[NL * 2 * D];      // per-layer [sum|sumsq]
__device__ __align__(16) int   g_bsum[64];
__device__ __align__(16) float g_wt[NL * 2 * D * D];     // W^T, tf32-rounded fp32
__device__ int g_is32;

__device__ __forceinline__ uint32_t f2tf32(float v) {
    uint32_t r;
    asm("cvt.rna.tf32.f32 %0, %1;" : "=r"(r) : "f"(v));
    return r;
}

// ---------------- init: weight pre-round (tf32, transposed) + detect + zeros ----
__global__ void k_init(const float* __restrict__ W1, const float* __restrict__ W2,
                       const long long* __restrict__ ei) {
    int b = blockIdx.x, tid = threadIdx.x;
    if (b < 6) {                       // W^T tf32: wt[b][n][k] = rna(W[k][n])
        int l = b >> 1, m = b & 1;
        const float* W = (m ? W2 : W1) + l * D * D;
        float* wt = g_wt + b * D * D;
        for (int idx = tid; idx < D * D; idx += 256) {
            int k = idx >> 7, n = idx & 127;
            wt[n * D + k] = __uint_as_float(f2tf32(W[idx]));
        }
    } else if (b == 6) {               // dtype sniff + BN stats zero
        if (tid == 0) {
            int is32 = 0;
            for (int i = 0; i < 64; i++) {
                long long v = ei[i];
                if (v < 0 || v >= N_NODES) { is32 = 1; break; }
            }
            g_is32 = is32;
        }
        for (int s = tid; s < NL * 2 * D; s += 256) g_stats[s] = 0.f;
    } else {                           // zero degree counters
        int i = (b - 7) * 256 + tid;
        if (i < N_NODES) g_cur[i] = 0;
    }
}

// ---------------- CSR build ----------------
// hist: 4 edges per thread, vectorized loads
__global__ void k_hist(const void* __restrict__ eiraw) {
    int e0 = (blockIdx.x * blockDim.x + threadIdx.x) * 4;
    if (e0 >= N_EDGES) return;
    int d4[4];
    if (g_is32) {
        int4 v = *(const int4*)((const int*)eiraw + N_EDGES + e0);
        d4[0] = v.x; d4[1] = v.y; d4[2] = v.z; d4[3] = v.w;
    } else {
        const long long* p = (const long long*)eiraw + N_EDGES + e0;
        longlong2 v0 = *(const longlong2*)p;
        longlong2 v1 = *(const longlong2*)(p + 2);
        d4[0] = (int)v0.x; d4[1] = (int)v0.y; d4[2] = (int)v1.x; d4[3] = (int)v1.y;
    }
#pragma unroll
    for (int u = 0; u < 4; u++)
        if ((unsigned)d4[u] < N_NODES) atomicAdd(&g_cur[d4[u]], 1);
}

// warp-shuffle block scan (1024 threads, 32 warps)
__global__ void k_scan1() {
    __shared__ int wsum[32];
    int b = blockIdx.x, tid = threadIdx.x;
    int lane = tid & 31, wrp = tid >> 5;
    int i = b * 1024 + tid;
    int v = (i < N_NODES) ? g_cur[i] : 0;
    int x = v;
#pragma unroll
    for (int d = 1; d < 32; d <<= 1) {
        int t = __shfl_up_sync(0xFFFFFFFF, x, d);
        if (lane >= d) x += t;
    }
    if (lane == 31) wsum[wrp] = x;
    __syncthreads();
    if (wrp == 0) {
        int y = wsum[lane];
#pragma unroll
        for (int d = 1; d < 32; d <<= 1) {
            int t = __shfl_up_sync(0xFFFFFFFF, y, d);
            if (lane >= d) y += t;
        }
        wsum[lane] = y;
    }
    __syncthreads();
    int incl = x + (wrp > 0 ? wsum[wrp - 1] : 0);
    if (i < N_NODES) g_off[i] = incl - v;    // block-local exclusive
    if (tid == 1023) g_bsum[b] = incl;
}

// fused cross-block prefix + fixup
__global__ void k_scan3() {
    __shared__ int pre;
    if (threadIdx.x == 0) {
        int acc = 0;
        for (int b = 0; b < blockIdx.x; b++) acc += g_bsum[b];
        pre = acc;
        if (blockIdx.x == 48) g_off[N_NODES] = acc + g_bsum[48];
    }
    __syncthreads();
    int i = blockIdx.x * 1024 + threadIdx.x;
    if (i < N_NODES) {
        int o = g_off[i] + pre;
        g_off[i] = o;
        g_cur[i] = o;
    }
}

// scatter: 4 edges per thread, vectorized loads
__global__ void k_scatter(const void* __restrict__ eiraw, const float* __restrict__ ew) {
    int e0 = (blockIdx.x * blockDim.x + threadIdx.x) * 4;
    if (e0 >= N_EDGES) return;
    int s4[4], d4[4];
    if (g_is32) {
        const int* p = (const int*)eiraw;
        int4 sv = *(const int4*)(p + e0);
        int4 dv = *(const int4*)(p + N_EDGES + e0);
        s4[0] = sv.x; s4[1] = sv.y; s4[2] = sv.z; s4[3] = sv.w;
        d4[0] = dv.x; d4[1] = dv.y; d4[2] = dv.z; d4[3] = dv.w;
    } else {
        const long long* p = (const long long*)eiraw;
        longlong2 s0 = *(const longlong2*)(p + e0);
        longlong2 s1 = *(const longlong2*)(p + e0 + 2);
        longlong2 t0 = *(const longlong2*)(p + N_EDGES + e0);
        longlong2 t1 = *(const longlong2*)(p + N_EDGES + e0 + 2);
        s4[0] = (int)s0.x; s4[1] = (int)s0.y; s4[2] = (int)s1.x; s4[3] = (int)s1.y;
        d4[0] = (int)t0.x; d4[1] = (int)t0.y; d4[2] = (int)t1.x; d4[3] = (int)t1.y;
    }
    float4 wv = *(const float4*)(ew + e0);
    float w4[4] = {wv.x, wv.y, wv.z, wv.w};
#pragma unroll
    for (int u = 0; u < 4; u++) {
        if ((unsigned)s4[u] >= N_NODES || (unsigned)d4[u] >= N_NODES) continue;
        int q = atomicAdd(&g_cur[d4[u]], 1);
        g_srcs[q] = s4[u];
        g_ws[q] = w4[u];
    }
}

// ---------------- aggregation + GIN-combine fused ----------------
// one warp per node, 8 gathers in flight; writes A = tf32((1+eps)*x + agg)
__global__ __launch_bounds__(256) void k_agg(const float* __restrict__ xin,
                                             const float* __restrict__ epsv, int layer) {
    int warp = (blockIdx.x * blockDim.x + threadIdx.x) >> 5;
    int lane = threadIdx.x & 31;
    if (warp >= N_NODES) return;
    int beg = g_off[warp];
    int end = g_off[warp + 1];
    float4 acc = make_float4(0.f, 0.f, 0.f, 0.f);
    const float4* xr = (const float4*)xin;
    int j = beg;
    for (; j + 8 <= end; j += 8) {
        int   s[8];
        float w[8];
#pragma unroll
        for (int u = 0; u < 8; u++) { s[u] = g_srcs[j + u]; w[u] = g_ws[j + u]; }
        float4 v[8];
#pragma unroll
        for (int u = 0; u < 8; u++) v[u] = xr[s[u] * (D / 4) + lane];
#pragma unroll
        for (int u = 0; u < 8; u++) {
            acc.x += w[u] * v[u].x;
            acc.y += w[u] * v[u].y;
            acc.z += w[u] * v[u].z;
            acc.w += w[u] * v[u].w;
        }
    }
    for (; j + 2 <= end; j += 2) {
        int s0 = g_srcs[j];     float w0 = g_ws[j];
        int s1 = g_srcs[j + 1]; float w1 = g_ws[j + 1];
        float4 v0 = xr[s0 * (D / 4) + lane];
        float4 v1 = xr[s1 * (D / 4) + lane];
        acc.x += w0 * v0.x + w1 * v1.x;
        acc.y += w0 * v0.y + w1 * v1.y;
        acc.z += w0 * v0.z + w1 * v1.z;
        acc.w += w0 * v0.w + w1 * v1.w;
    }
    if (j < end) {
        int s0 = g_srcs[j]; float w0 = g_ws[j];
        float4 v0 = xr[s0 * (D / 4) + lane];
        acc.x += w0 * v0.x; acc.y += w0 * v0.y;
        acc.z += w0 * v0.z; acc.w += w0 * v0.w;
    }
    // fuse GIN combine: A = tf32((1+eps)*x[node] + agg)
    float e1 = 1.0f + epsv[layer];
    float4 xv = xr[warp * (D / 4) + lane];
    float4 t;
    t.x = __uint_as_float(f2tf32(e1 * xv.x + acc.x));
    t.y = __uint_as_float(f2tf32(e1 * xv.y + acc.y));
    t.z = __uint_as_float(f2tf32(e1 * xv.z + acc.z));
    t.w = __uint_as_float(f2tf32(e1 * xv.w + acc.w));
    ((float4*)g_agg)[warp * (D / 4) + lane] = t;
}

// ---------------- single-pass tf32 mma.sync fused MLP ----------------
// 512 threads, 4x4 warp grid (warp tile 32x32), 128-row tile, 1 CTA/SM.
// smem: sA [128][132] @ 0, sB1 (W1^T) @ 67584, sB2 (W2^T) @ 135168 — both
// weights staged up-front (kills the mid-chain W2 stage + one sync).
// sT (128x129 f32) aliases sB1; BN-reduce arrays alias sA.  total 202752B.
#define SROW 132
#define OFF_A  0
#define OFF_B1 67584
#define OFF_B2 135168
#define SMEM_TOT 202752

__device__ __forceinline__ void mma_tf32(float* d, const uint32_t* a,
                                         uint32_t b0, uint32_t b1) {
    asm volatile(
        "mma.sync.aligned.m16n8k8.row.col.f32.tf32.tf32.f32 "
        "{%0,%1,%2,%3}, {%4,%5,%6,%7}, {%8,%9}, {%0,%1,%2,%3};"
        : "+f"(d[0]), "+f"(d[1]), "+f"(d[2]), "+f"(d[3])
        : "r"(a[0]), "r"(a[1]), "r"(a[2]), "r"(a[3]), "r"(b0), "r"(b1));
}

// 128x128x128 GEMM, single tf32 pass, into d[2][4][4]; warp tile 32x32
__device__ __forceinline__ void gemm_tf32(const char* sm, int boff, float d[2][4][4],
                                          int rbase, int cbase, int lane) {
    int gr = lane >> 2;
    int tg = lane & 3;
    const uint32_t* A = (const uint32_t*)(sm + OFF_A);
    const uint32_t* B = (const uint32_t*)(sm + boff);
#pragma unroll
    for (int k0 = 0; k0 < 16; k0++) {
        int kc = k0 * 8;
        uint32_t a[2][4];
#pragma unroll
        for (int mf = 0; mf < 2; mf++) {
            int r0 = rbase + mf * 16 + gr;
            a[mf][0] = A[r0 * SROW + kc + tg];
            a[mf][1] = A[(r0 + 8) * SROW + kc + tg];
            a[mf][2] = A[r0 * SROW + kc + tg + 4];
            a[mf][3] = A[(r0 + 8) * SROW + kc + tg + 4];
        }
#pragma unroll
        for (int nf = 0; nf < 4; nf++) {
            int n0 = cbase + nf * 8 + gr;
            uint32_t b0 = B[n0 * SROW + kc + tg];
            uint32_t b1 = B[n0 * SROW + kc + tg + 4];
            mma_tf32(d[0][nf], a[0], b0, b1);
            mma_tf32(d[1][nf], a[1], b0, b1);
        }
    }
}

__global__ __launch_bounds__(512, 1) void k_mlp(
    const float* __restrict__ b1, const float* __restrict__ b2, int layer) {
    extern __shared__ char sm[];
    int tid = threadIdx.x, lane = tid & 31, wid = tid >> 5;
    int m0 = blockIdx.x * 128;
    int wm = wid >> 2, wn = wid & 3;          // 4 x 4 warp grid
    int rbase = wm * 32, cbase = wn * 32;
    int gr = lane >> 2, tg2 = (lane & 3) * 2;

    float* sA  = (float*)(sm + OFF_A);
    float* sB1 = (float*)(sm + OFF_B1);
    float* sB2 = (float*)(sm + OFF_B2);

    // ---- stage A (pre-fused g_agg rows) + BOTH weight matrices ----
    for (int idx = tid * 4; idx < D * D; idx += 2048) {
        int r = idx >> 7, c = idx & 127;
        int gro = m0 + r;
        float4 v = make_float4(0.f, 0.f, 0.f, 0.f);
        if (gro < N_NODES) v = *(const float4*)(g_agg + gro * D + c);
        *(float4*)&sA[r * SROW + c] = v;
    }
    {
        const float* wt1 = g_wt + (layer * 2 + 0) * D * D;
        const float* wt2 = g_wt + (layer * 2 + 1) * D * D;
        for (int idx = tid * 4; idx < D * D; idx += 2048) {
            int n = idx >> 7, k = idx & 127;
            *(float4*)&sB1[n * SROW + k] = *(const float4*)&wt1[idx];
            *(float4*)&sB2[n * SROW + k] = *(const float4*)&wt2[idx];
        }
    }
    __syncthreads();

    // ---- GEMM1: H1 = A @ W1 ----
    float d[2][4][4];
#pragma unroll
    for (int mf = 0; mf < 2; mf++)
#pragma unroll
        for (int nf = 0; nf < 4; nf++)
#pragma unroll
            for (int q = 0; q < 4; q++) d[mf][nf][q] = 0.f;
    gemm_tf32(sm, OFF_B1, d, rbase, cbase, lane);
    __syncthreads();

    // ---- epilogue1: tf32(relu(H1 + b1)) -> back into sA ----
    {
        const float* bb = b1 + layer * D;
#pragma unroll
        for (int mf = 0; mf < 2; mf++) {
            int r0 = rbase + mf * 16 + gr;
#pragma unroll
            for (int nf = 0; nf < 4; nf++) {
                int col = cbase + nf * 8 + tg2;
                float bv0 = bb[col], bv1 = bb[col + 1];
                sA[r0 * SROW + col]           = __uint_as_float(f2tf32(fmaxf(d[mf][nf][0] + bv0, 0.f)));
                sA[r0 * SROW + col + 1]       = __uint_as_float(f2tf32(fmaxf(d[mf][nf][1] + bv1, 0.f)));
                sA[(r0 + 8) * SROW + col]     = __uint_as_float(f2tf32(fmaxf(d[mf][nf][2] + bv0, 0.f)));
                sA[(r0 + 8) * SROW + col + 1] = __uint_as_float(f2tf32(fmaxf(d[mf][nf][3] + bv1, 0.f)));
            }
        }
    }
    __syncthreads();

    // ---- GEMM2: H2 = relu(H1) @ W2 ----
#pragma unroll
    for (int mf = 0; mf < 2; mf++)
#pragma unroll
        for (int nf = 0; nf < 4; nf++)
#pragma unroll
            for (int q = 0; q < 4; q++) d[mf][nf][q] = 0.f;
    gemm_tf32(sm, OFF_B2, d, rbase, cbase, lane);
    __syncthreads();

    // ---- epilogue2: h = H2 + b2 -> sT (zero OOB rows; aliases dead sB1) ----
    float* sT = (float*)(sm + OFF_B1);   // 128 x 129 floats = 66048B <= 67584B
    {
        const float* bb = b2 + layer * D;
#pragma unroll
        for (int mf = 0; mf < 2; mf++) {
            int r0 = rbase + mf * 16 + gr;
            bool v0ok = (m0 + r0) < N_NODES;
            bool v1ok = (m0 + r0 + 8) < N_NODES;
#pragma unroll
            for (int nf = 0; nf < 4; nf++) {
                int col = cbase + nf * 8 + tg2;
                float bv0 = bb[col], bv1 = bb[col + 1];
                sT[r0 * 129 + col]           = v0ok ? d[mf][nf][0] + bv0 : 0.f;
                sT[r0 * 129 + col + 1]       = v0ok ? d[mf][nf][1] + bv1 : 0.f;
                sT[(r0 + 8) * 129 + col]     = v1ok ? d[mf][nf][2] + bv0 : 0.f;
                sT[(r0 + 8) * 129 + col + 1] = v1ok ? d[mf][nf][3] + bv1 : 0.f;
            }
        }
    }
    __syncthreads();

    // ---- BN column partial sums: 4 row-quarters per column (alias sA) ----
    float* sRedS = (float*)(sm + OFF_A);         // 512 floats
    float* sRedQ = (float*)(sm + OFF_A) + 512;   // 512 floats
    {
        int col = tid & 127, rq = tid >> 7;
        float s = 0.f, q = 0.f;
        int rlo = rq * 32;
#pragma unroll 4
        for (int r = rlo; r < rlo + 32; r++) {
            float h = sT[r * 129 + col];
            s += h; q += h * h;
        }
        sRedS[rq * 128 + col] = s;
        sRedQ[rq * 128 + col] = q;
    }
    __syncthreads();
    float* stats = g_stats + layer * 2 * D;
    if (tid < 128) {
        atomicAdd(&stats[tid],
                  sRedS[tid] + sRedS[128 + tid] + sRedS[256 + tid] + sRedS[384 + tid]);
    } else if (tid < 256) {
        int c = tid - 128;
        atomicAdd(&stats[128 + c],
                  sRedQ[c] + sRedQ[128 + c] + sRedQ[256 + c] + sRedQ[384 + c]);
    }
    // ---- coalesced g_h store ----
    for (int idx = tid; idx < 4096; idx += 512) {
        int r = idx >> 5, c4 = (idx & 31) << 2;
        int gro = m0 + r;
        if (gro < N_NODES) {
            float4 o = make_float4(sT[r * 129 + c4], sT[r * 129 + c4 + 1],
                                   sT[r * 129 + c4 + 2], sT[r * 129 + c4 + 3]);
            *(float4*)(g_h + gro * D + c4) = o;
        }
    }
}

// ---------------- BN apply + relu + residual ----------------
__global__ void k_bn(const float* __restrict__ xin, float* __restrict__ xout,
                     const float* __restrict__ gamma, const float* __restrict__ beta,
                     int layer) {
    int idx = blockIdx.x * blockDim.x + threadIdx.x;
    if (idx >= N_NODES * D / 4) return;
    int c = (idx & 31) * 4;
    const float* stats = g_stats + layer * 2 * D;
    float4 s  = *(const float4*)(stats + c);
    float4 sq = *(const float4*)(stats + D + c);
    float4 g  = *(const float4*)(gamma + layer * D + c);
    float4 be = *(const float4*)(beta + layer * D + c);
    float4 h  = ((const float4*)g_h)[idx];
    float4 xv = ((const float4*)xin)[idx];
    const float inv = 1.0f / (float)N_NODES;
    float4 o;
    { float mu = s.x * inv, var = sq.x * inv - mu * mu, r = rsqrtf(var + BN_EPSF);
      o.x = xv.x + fmaxf(g.x * (h.x - mu) * r + be.x, 0.f); }
    { float mu = s.y * inv, var = sq.y * inv - mu * mu, r = rsqrtf(var + BN_EPSF);
      o.y = xv.y + fmaxf(g.y * (h.y - mu) * r + be.y, 0.f); }
    { float mu = s.z * inv, var = sq.z * inv - mu * mu, r = rsqrtf(var + BN_EPSF);
      o.z = xv.z + fmaxf(g.z * (h.z - mu) * r + be.z, 0.f); }
    { float mu = s.w * inv, var = sq.w * inv - mu * mu, r = rsqrtf(var + BN_EPSF);
      o.w = xv.w + fmaxf(g.w * (h.w - mu) * r + be.w, 0.f); }
    ((float4*)xout)[idx] = o;
}

// ---------------- launch ----------------
extern "C" void kernel_launch(void* const* d_in, const int* in_sizes, int n_in,
                              void* d_out, int out_size) {
    const float* x     = (const float*)d_in[0];
    const void*  eiraw = d_in[1];
    const float* ew    = (const float*)d_in[3];
    const float* W1    = (const float*)d_in[4];
    const float* b1    = (const float*)d_in[5];
    const float* W2    = (const float*)d_in[6];
    const float* b2    = (const float*)d_in[7];
    const float* eps   = (const float*)d_in[8];
    const float* gamma = (const float*)d_in[9];
    const float* beta  = (const float*)d_in[10];
    float* out = (float*)d_out;

    cudaFuncSetAttribute(k_mlp, cudaFuncAttributeMaxDynamicSharedMemorySize, SMEM_TOT);

    float* gx = nullptr;
    cudaGetSymbolAddress((void**)&gx, g_x);

    k_init<<<7 + (N_NODES + 255) / 256, 256>>>(W1, W2, (const long long*)eiraw);
    k_hist<<<(N_EDGES / 4 + 255) / 256, 256>>>(eiraw);
    k_scan1<<<49, 1024>>>();
    k_scan3<<<49, 1024>>>();
    k_scatter<<<(N_EDGES / 4 + 255) / 256, 256>>>(eiraw, ew);

    const int n_mlp_blk = (N_NODES + 127) / 128;
    const float* xin = x;
    for (int l = 0; l < NL; l++) {
        k_agg<<<(N_NODES + 7) / 8, 256>>>(xin, eps, l);
        k_mlp<<<n_mlp_blk, 512, SMEM_TOT>>>(b1, b2, l);
        float* xout = (l == NL - 1) ? out : gx;
        k_bn<<<(N_NODES * D / 4 + 255) / 256, 256>>>(xin, xout, gamma, beta, l);
        xin = xout;
    }
}